// round 1
// baseline (speedup 1.0000x reference)
#include <cuda_runtime.h>
#include <math.h>
#include <math_constants.h>

// Problem constants
#define BATCH 2
#define SEQ   4096
#define EDIM  1024
#define HDIM  1024
#define MTOT  (BATCH * SEQ)   // 8192

// GEMM tiling
#define BM 128
#define BN 128
#define BK 16
#define TM 8
#define TN 8
#define NTHREADS 256

// Scratch (device globals: allocation-free per harness rules)
__device__ float g_Q[(size_t)MTOT * HDIM];
__device__ float g_K[(size_t)MTOT * HDIM];
__device__ float g_V[(size_t)MTOT * HDIM];
__device__ float g_P[(size_t)BATCH * SEQ * SEQ];

// ---------------------------------------------------------------------------
// Fused QKV projection: C = X @ W^T + b   (NT layout: both operands K-major)
// grid = (HDIM/BN, MTOT/BM, 3); z selects {Q,K,V}
// ---------------------------------------------------------------------------
__global__ __launch_bounds__(NTHREADS) void qkv_kernel(
    const float* __restrict__ X,
    const float* __restrict__ Wq, const float* __restrict__ bq,
    const float* __restrict__ Wk, const float* __restrict__ bk,
    const float* __restrict__ Wv, const float* __restrict__ bv)
{
    const float* W; const float* bias; float* Cout;
    if (blockIdx.z == 0)      { W = Wq; bias = bq; Cout = g_Q; }
    else if (blockIdx.z == 1) { W = Wk; bias = bk; Cout = g_K; }
    else                      { W = Wv; bias = bv; Cout = g_V; }

    __shared__ float As[BK][BM];
    __shared__ float Bs[BK][BN];

    const int tid = threadIdx.x;
    const int tx = tid & 15, ty = tid >> 4;
    const int tm0 = ty * TM, tn0 = tx * TN;
    const int row0 = blockIdx.y * BM;
    const int col0 = blockIdx.x * BN;

    const float* Ab = X + (size_t)row0 * EDIM;
    const float* Bb = W + (size_t)col0 * EDIM;

    float acc[TM][TN] = {};

    for (int k0 = 0; k0 < EDIM; k0 += BK) {
        // 512 float4 per tile side, 256 threads -> 2 each
        #pragma unroll
        for (int it = 0; it < 2; it++) {
            int i = tid + it * NTHREADS;
            int r = i >> 2, c = (i & 3) << 2;
            float4 va = *(const float4*)(Ab + (size_t)r * EDIM + k0 + c);
            As[c + 0][r] = va.x; As[c + 1][r] = va.y;
            As[c + 2][r] = va.z; As[c + 3][r] = va.w;
            float4 vb = *(const float4*)(Bb + (size_t)r * EDIM + k0 + c);
            Bs[c + 0][r] = vb.x; Bs[c + 1][r] = vb.y;
            Bs[c + 2][r] = vb.z; Bs[c + 3][r] = vb.w;
        }
        __syncthreads();

        #pragma unroll
        for (int kk = 0; kk < BK; kk++) {
            float a0[TM], b0[TN];
            #pragma unroll
            for (int i = 0; i < TM; i++) a0[i] = As[kk][tm0 + i];
            #pragma unroll
            for (int j = 0; j < TN; j++) b0[j] = Bs[kk][tn0 + j];
            #pragma unroll
            for (int i = 0; i < TM; i++)
                #pragma unroll
                for (int j = 0; j < TN; j++)
                    acc[i][j] = fmaf(a0[i], b0[j], acc[i][j]);
        }
        __syncthreads();
    }

    float bvals[TN];
    #pragma unroll
    for (int j = 0; j < TN; j++) bvals[j] = bias[col0 + tn0 + j];

    #pragma unroll
    for (int i = 0; i < TM; i++) {
        float* crow = Cout + (size_t)(row0 + tm0 + i) * HDIM + col0 + tn0;
        #pragma unroll
        for (int j = 0; j < TN; j += 4) {
            float4 v;
            v.x = acc[i][j + 0] + bvals[j + 0];
            v.y = acc[i][j + 1] + bvals[j + 1];
            v.z = acc[i][j + 2] + bvals[j + 2];
            v.w = acc[i][j + 3] + bvals[j + 3];
            *(float4*)(crow + j) = v;
        }
    }
}

// ---------------------------------------------------------------------------
// Scores: P[b,q,k] = (Q[b,q,:] . K[b,k,:]) / sqrt(H), mask==0 -> -inf
// grid = (SEQ/BN, SEQ/BM, BATCH)
// ---------------------------------------------------------------------------
__global__ __launch_bounds__(NTHREADS) void scores_kernel(
    const int* __restrict__ mask)
{
    __shared__ float As[BK][BM];
    __shared__ float Bs[BK][BN];

    const int tid = threadIdx.x;
    const int tx = tid & 15, ty = tid >> 4;
    const int tm0 = ty * TM, tn0 = tx * TN;
    const int b = blockIdx.z;
    const int row0 = blockIdx.y * BM;
    const int col0 = blockIdx.x * BN;

    const float* Ab = g_Q + (size_t)b * SEQ * HDIM + (size_t)row0 * HDIM;
    const float* Bb = g_K + (size_t)b * SEQ * HDIM + (size_t)col0 * HDIM;

    float acc[TM][TN] = {};

    for (int k0 = 0; k0 < HDIM; k0 += BK) {
        #pragma unroll
        for (int it = 0; it < 2; it++) {
            int i = tid + it * NTHREADS;
            int r = i >> 2, c = (i & 3) << 2;
            float4 va = *(const float4*)(Ab + (size_t)r * HDIM + k0 + c);
            As[c + 0][r] = va.x; As[c + 1][r] = va.y;
            As[c + 2][r] = va.z; As[c + 3][r] = va.w;
            float4 vb = *(const float4*)(Bb + (size_t)r * HDIM + k0 + c);
            Bs[c + 0][r] = vb.x; Bs[c + 1][r] = vb.y;
            Bs[c + 2][r] = vb.z; Bs[c + 3][r] = vb.w;
        }
        __syncthreads();

        #pragma unroll
        for (int kk = 0; kk < BK; kk++) {
            float a0[TM], b0[TN];
            #pragma unroll
            for (int i = 0; i < TM; i++) a0[i] = As[kk][tm0 + i];
            #pragma unroll
            for (int j = 0; j < TN; j++) b0[j] = Bs[kk][tn0 + j];
            #pragma unroll
            for (int i = 0; i < TM; i++)
                #pragma unroll
                for (int j = 0; j < TN; j++)
                    acc[i][j] = fmaf(a0[i], b0[j], acc[i][j]);
        }
        __syncthreads();
    }

    const float scale = 0.03125f;  // 1/sqrt(1024)
    const size_t pbase = (size_t)b * SEQ * SEQ;
    #pragma unroll
    for (int i = 0; i < TM; i++) {
        size_t roff = pbase + (size_t)(row0 + tm0 + i) * SEQ + col0 + tn0;
        #pragma unroll
        for (int j = 0; j < TN; j++) {
            float v = acc[i][j] * scale;
            int m = mask[roff + j];
            g_P[roff + j] = (m == 0) ? -CUDART_INF_F : v;
        }
    }
}

// ---------------------------------------------------------------------------
// Row softmax over g_P, in place. One block per row (BATCH*SEQ rows).
// ---------------------------------------------------------------------------
__global__ __launch_bounds__(256) void softmax_kernel()
{
    __shared__ float buf[SEQ];
    __shared__ float red[8];

    const int tid = threadIdx.x;
    float* p = g_P + (size_t)blockIdx.x * SEQ;

    float m = -CUDART_INF_F;
    #pragma unroll
    for (int i = tid; i < SEQ; i += 256) {
        float v = p[i];
        buf[i] = v;
        m = fmaxf(m, v);
    }
    #pragma unroll
    for (int o = 16; o; o >>= 1) m = fmaxf(m, __shfl_xor_sync(0xFFFFFFFFu, m, o));
    if ((tid & 31) == 0) red[tid >> 5] = m;
    __syncthreads();
    m = red[0];
    #pragma unroll
    for (int w = 1; w < 8; w++) m = fmaxf(m, red[w]);
    __syncthreads();

    float s = 0.0f;
    #pragma unroll
    for (int i = tid; i < SEQ; i += 256) {
        float e = __expf(buf[i] - m);
        buf[i] = e;
        s += e;
    }
    #pragma unroll
    for (int o = 16; o; o >>= 1) s += __shfl_xor_sync(0xFFFFFFFFu, s, o);
    if ((tid & 31) == 0) red[tid >> 5] = s;
    __syncthreads();
    s = red[0];
    #pragma unroll
    for (int w = 1; w < 8; w++) s += red[w];
    float inv = 1.0f / s;

    #pragma unroll
    for (int i = tid; i < SEQ; i += 256) p[i] = buf[i] * inv;
}

// ---------------------------------------------------------------------------
// Output: out[b,q,h] = sum_k P[b,q,k] * V[b,k,h]   (NN layout)
// grid = (HDIM/BN, SEQ/BM, BATCH)
// ---------------------------------------------------------------------------
__global__ __launch_bounds__(NTHREADS) void out_kernel(float* __restrict__ out)
{
    __shared__ float As[BK][BM];
    __shared__ float Bs[BK][BN];

    const int tid = threadIdx.x;
    const int tx = tid & 15, ty = tid >> 4;
    const int tm0 = ty * TM, tn0 = tx * TN;
    const int b = blockIdx.z;
    const int row0 = blockIdx.y * BM;
    const int col0 = blockIdx.x * BN;

    const float* Ab = g_P + (size_t)b * SEQ * SEQ + (size_t)row0 * SEQ;
    const float* Bb = g_V + (size_t)b * SEQ * HDIM + col0;

    float acc[TM][TN] = {};

    for (int k0 = 0; k0 < SEQ; k0 += BK) {
        #pragma unroll
        for (int it = 0; it < 2; it++) {
            int i = tid + it * NTHREADS;
            // A tile: [BM rows][BK k], K-contiguous
            int r = i >> 2, c = (i & 3) << 2;
            float4 va = *(const float4*)(Ab + (size_t)r * SEQ + k0 + c);
            As[c + 0][r] = va.x; As[c + 1][r] = va.y;
            As[c + 2][r] = va.z; As[c + 3][r] = va.w;
            // B tile: [BK k][BN n], N-contiguous
            int kk = i >> 5, cn = (i & 31) << 2;
            float4 vb = *(const float4*)(Bb + (size_t)(k0 + kk) * HDIM + cn);
            *(float4*)&Bs[kk][cn] = vb;
        }
        __syncthreads();

        #pragma unroll
        for (int kk = 0; kk < BK; kk++) {
            float a0[TM], b0[TN];
            #pragma unroll
            for (int i = 0; i < TM; i++) a0[i] = As[kk][tm0 + i];
            #pragma unroll
            for (int j = 0; j < TN; j++) b0[j] = Bs[kk][tn0 + j];
            #pragma unroll
            for (int i = 0; i < TM; i++)
                #pragma unroll
                for (int j = 0; j < TN; j++)
                    acc[i][j] = fmaf(a0[i], b0[j], acc[i][j]);
        }
        __syncthreads();
    }

    float* obase = out + (size_t)b * SEQ * HDIM;
    #pragma unroll
    for (int i = 0; i < TM; i++) {
        float* crow = obase + (size_t)(row0 + tm0 + i) * HDIM + col0 + tn0;
        #pragma unroll
        for (int j = 0; j < TN; j += 4) {
            float4 v;
            v.x = acc[i][j + 0]; v.y = acc[i][j + 1];
            v.z = acc[i][j + 2]; v.w = acc[i][j + 3];
            *(float4*)(crow + j) = v;
        }
    }
}

// ---------------------------------------------------------------------------
extern "C" void kernel_launch(void* const* d_in, const int* in_sizes, int n_in,
                              void* d_out, int out_size)
{
    const float* X    = (const float*)d_in[0];
    const int*   mask = (const int*)  d_in[1];
    const float* Wq   = (const float*)d_in[2];
    const float* bq   = (const float*)d_in[3];
    const float* Wk   = (const float*)d_in[4];
    const float* bk   = (const float*)d_in[5];
    const float* Wv   = (const float*)d_in[6];
    const float* bv   = (const float*)d_in[7];
    float* out = (float*)d_out;

    dim3 blk(NTHREADS);

    dim3 g_qkv(HDIM / BN, MTOT / BM, 3);          // 8 x 64 x 3
    qkv_kernel<<<g_qkv, blk>>>(X, Wq, bq, Wk, bk, Wv, bv);

    dim3 g_sc(SEQ / BN, SEQ / BM, BATCH);         // 32 x 32 x 2
    scores_kernel<<<g_sc, blk>>>(mask);

    softmax_kernel<<<BATCH * SEQ, 256>>>();       // 8192 rows

    dim3 g_out(HDIM / BN, SEQ / BM, BATCH);       // 8 x 32 x 2
    out_kernel<<<g_out, blk>>>(out);
}

// round 3
// speedup vs baseline: 3.1172x; 3.1172x over previous
#include <cuda_runtime.h>
#include <cuda_bf16.h>
#include <cstdint>
#include <math_constants.h>

#define E    1024
#define H    1024
#define SQ   4096
#define NB   2
#define MTOT 8192
#define NT   256
#define SMEM_DYN 131072

// ---------------------------------------------------------------------------
// Device scratch (allocation-free per harness rules)
// ---------------------------------------------------------------------------
__device__ __align__(256) __nv_bfloat16 g_Xhi[(size_t)MTOT * E];
__device__ __align__(256) __nv_bfloat16 g_Xlo[(size_t)MTOT * E];
__device__ __align__(256) __nv_bfloat16 g_Whi[(size_t)3 * H * E];
__device__ __align__(256) __nv_bfloat16 g_Wlo[(size_t)3 * H * E];
__device__ __align__(256) __nv_bfloat16 g_Qhi[(size_t)MTOT * H];
__device__ __align__(256) __nv_bfloat16 g_Qlo[(size_t)MTOT * H];
__device__ __align__(256) __nv_bfloat16 g_Khi[(size_t)MTOT * H];
__device__ __align__(256) __nv_bfloat16 g_Klo[(size_t)MTOT * H];
__device__ __align__(256) __nv_bfloat16 g_Vthi[(size_t)NB * H * SQ]; // [b][h][s]
__device__ __align__(256) __nv_bfloat16 g_Vtlo[(size_t)NB * H * SQ];
__device__ __align__(256) float         g_P  [(size_t)NB * SQ * SQ];
__device__ __align__(256) __nv_bfloat16 g_Phi[(size_t)NB * SQ * SQ];
__device__ __align__(256) __nv_bfloat16 g_Plo[(size_t)NB * SQ * SQ];

// ---------------------------------------------------------------------------
// Helpers
// ---------------------------------------------------------------------------
__device__ __forceinline__ uint32_t smem_u32(const void* p) {
    uint32_t a;
    asm("{ .reg .u64 t; cvta.to.shared.u64 t, %1; cvt.u32.u64 %0, t; }"
        : "=r"(a) : "l"(p));
    return a;
}

#define SWZ(o) ((o) ^ (((o) >> 3) & 0x70))

__device__ __forceinline__ void cpa16(uint32_t dst, const void* src) {
    asm volatile("cp.async.cg.shared.global [%0], [%1], 16;" :: "r"(dst), "l"(src));
}
#define CP_COMMIT() asm volatile("cp.async.commit_group;" ::: "memory")
#define CP_WAIT1()  asm volatile("cp.async.wait_group 1;" ::: "memory")
#define CP_WAIT0()  asm volatile("cp.async.wait_group 0;" ::: "memory")

__device__ __forceinline__ void ldsm4(uint32_t r[4], uint32_t addr) {
    asm volatile("ldmatrix.sync.aligned.m8n8.x4.shared.b16 {%0,%1,%2,%3}, [%4];"
                 : "=r"(r[0]), "=r"(r[1]), "=r"(r[2]), "=r"(r[3]) : "r"(addr));
}

__device__ __forceinline__ void mma16816(float* d, const uint32_t* a,
                                         uint32_t b0, uint32_t b1) {
    asm volatile(
        "mma.sync.aligned.m16n8k16.row.col.f32.bf16.bf16.f32 "
        "{%0,%1,%2,%3}, {%4,%5,%6,%7}, {%8,%9}, {%0,%1,%2,%3};"
        : "+f"(d[0]), "+f"(d[1]), "+f"(d[2]), "+f"(d[3])
        : "r"(a[0]), "r"(a[1]), "r"(a[2]), "r"(a[3]), "r"(b0), "r"(b1));
}

__device__ __forceinline__ void split2(float a, float b,
                                       __nv_bfloat162& h, __nv_bfloat162& l2) {
    h = __float22bfloat162_rn(make_float2(a, b));
    float2 hf = __bfloat1622float2(h);
    l2 = __float22bfloat162_rn(make_float2(a - hf.x, b - hf.y));
}

// Copy one 128x64 bf16 tile (K-major rows) into SW128-swizzled smem
__device__ __forceinline__ void fill_copy(uint32_t dst,
                                          const __nv_bfloat16* __restrict__ src,
                                          size_t ld, int tid) {
    #pragma unroll
    for (int i = 0; i < 4; i++) {
        int s = tid + i * NT;
        int r = s >> 3, q = s & 7;
        cpa16(dst + SWZ((uint32_t)(r * 128 + q * 16)),
              src + (size_t)r * ld + q * 8);
    }
}

// ---------------------------------------------------------------------------
// Shared NT GEMM mainloop: C[128x128] += (Ahi+Alo)(Bhi+Blo)^T, bf16x3.
// Both operands stored K-major (row = M or N index, cols = K).
// ---------------------------------------------------------------------------
__device__ __forceinline__ void gemm_main(
    const __nv_bfloat16* __restrict__ Ah, const __nv_bfloat16* __restrict__ Al,
    const __nv_bfloat16* __restrict__ Bh, const __nv_bfloat16* __restrict__ Bl,
    size_t lda, size_t ldb, int nkb, uint32_t sbuf, float (&acc)[2][8][4])
{
    const int tid = threadIdx.x, l = tid & 31, wid = tid >> 5;
    const int mw = (wid >> 1) * 32, nw = (wid & 1) * 64;
    // ldmatrix lane address offsets (bytes, pre-swizzle)
    const uint32_t aoff = (uint32_t)((mw + (l & 15)) * 128 + ((l >> 4) & 1) * 16);
    const uint32_t boff = (uint32_t)((nw + (l & 7) + ((l >> 4) & 1) * 8) * 128 +
                                     ((l >> 3) & 1) * 16);

    // Prologue: stage 0
    fill_copy(sbuf,         Ah, lda, tid);
    fill_copy(sbuf + 16384, Al, lda, tid);
    fill_copy(sbuf + 32768, Bh, ldb, tid);
    fill_copy(sbuf + 49152, Bl, ldb, tid);
    CP_COMMIT();

    for (int kb = 0; kb < nkb; kb++) {
        if (kb + 1 < nkb) {
            uint32_t nbuf = sbuf + ((kb + 1) & 1) * 65536;
            size_t ko = (size_t)(kb + 1) * 64;
            fill_copy(nbuf,         Ah + ko, lda, tid);
            fill_copy(nbuf + 16384, Al + ko, lda, tid);
            fill_copy(nbuf + 32768, Bh + ko, ldb, tid);
            fill_copy(nbuf + 49152, Bl + ko, ldb, tid);
            CP_COMMIT();
            CP_WAIT1();
        } else {
            CP_WAIT0();
        }
        __syncthreads();

        uint32_t base = sbuf + (kb & 1) * 65536;
        #pragma unroll
        for (int c = 0; c < 4; c++) {
            uint32_t ao = 32u * c;
            uint32_t ahi[2][4], alo[2][4];
            ldsm4(ahi[0], base +         SWZ(aoff + ao));
            ldsm4(ahi[1], base +         SWZ(aoff + 2048 + ao));
            ldsm4(alo[0], base + 16384 + SWZ(aoff + ao));
            ldsm4(alo[1], base + 16384 + SWZ(aoff + 2048 + ao));
            #pragma unroll
            for (int j = 0; j < 4; j++) {
                uint32_t bhi[4], blo[4];
                ldsm4(bhi, base + 32768 + SWZ(boff + j * 2048 + ao));
                ldsm4(blo, base + 49152 + SWZ(boff + j * 2048 + ao));
                #pragma unroll
                for (int mf = 0; mf < 2; mf++) {
                    mma16816(acc[mf][2*j],     ahi[mf], bhi[0], bhi[1]);
                    mma16816(acc[mf][2*j + 1], ahi[mf], bhi[2], bhi[3]);
                    mma16816(acc[mf][2*j],     ahi[mf], blo[0], blo[1]);
                    mma16816(acc[mf][2*j + 1], ahi[mf], blo[2], blo[3]);
                    mma16816(acc[mf][2*j],     alo[mf], bhi[0], bhi[1]);
                    mma16816(acc[mf][2*j + 1], alo[mf], bhi[2], bhi[3]);
                }
            }
        }
        __syncthreads();
    }
}

// Store register accumulators into padded fp32 stage (128 x 132)
__device__ __forceinline__ void store_stage(float* stage, float (&acc)[2][8][4]) {
    const int tid = threadIdx.x, l = tid & 31, wid = tid >> 5;
    const int mw = (wid >> 1) * 32, nw = (wid & 1) * 64;
    const int r0 = mw + (l >> 2), c0 = nw + (l & 3) * 2;
    #pragma unroll
    for (int mf = 0; mf < 2; mf++)
        #pragma unroll
        for (int nf = 0; nf < 8; nf++) {
            int cc = c0 + nf * 8;
            *(float2*)&stage[(r0 + mf * 16) * 132 + cc] =
                make_float2(acc[mf][nf][0], acc[mf][nf][1]);
            *(float2*)&stage[(r0 + mf * 16 + 8) * 132 + cc] =
                make_float2(acc[mf][nf][2], acc[mf][nf][3]);
        }
}

// ---------------------------------------------------------------------------
// Split fp32 -> (hi, lo) bf16
// ---------------------------------------------------------------------------
__global__ __launch_bounds__(NT) void split_k(const float* __restrict__ in,
                                              __nv_bfloat16* __restrict__ hi,
                                              __nv_bfloat16* __restrict__ lo,
                                              int n4)
{
    int i = blockIdx.x * NT + threadIdx.x;
    if (i >= n4) return;
    float4 v = ((const float4*)in)[i];
    __nv_bfloat162 h0, l0, h1, l1;
    split2(v.x, v.y, h0, l0);
    split2(v.z, v.w, h1, l1);
    ((__nv_bfloat162*)hi)[2 * i]     = h0;
    ((__nv_bfloat162*)hi)[2 * i + 1] = h1;
    ((__nv_bfloat162*)lo)[2 * i]     = l0;
    ((__nv_bfloat162*)lo)[2 * i + 1] = l1;
}

// ---------------------------------------------------------------------------
// QKV projection GEMM. grid (H/128, MTOT/128, 3)
// ---------------------------------------------------------------------------
__global__ __launch_bounds__(NT) void qkv_mm(const float* __restrict__ bq,
                                             const float* __restrict__ bk,
                                             const float* __restrict__ bv)
{
    extern __shared__ char dsm[];
    uint32_t sbuf = smem_u32(dsm);
    const int tid = threadIdx.x;
    const int z = blockIdx.z, row0 = blockIdx.y * 128, col0 = blockIdx.x * 128;

    const __nv_bfloat16* Ah = g_Xhi + (size_t)row0 * E;
    const __nv_bfloat16* Al = g_Xlo + (size_t)row0 * E;
    const __nv_bfloat16* Bh = g_Whi + ((size_t)z * H + col0) * E;
    const __nv_bfloat16* Bl = g_Wlo + ((size_t)z * H + col0) * E;

    float acc[2][8][4] = {};
    gemm_main(Ah, Al, Bh, Bl, E, E, E / 64, sbuf, acc);

    float* stage = (float*)dsm;
    store_stage(stage, acc);
    __syncthreads();

    const float* bias = (z == 0) ? bq : (z == 1) ? bk : bv;

    if (z < 2) {
        __nv_bfloat16* ohi = (z == 0) ? g_Qhi : g_Khi;
        __nv_bfloat16* olo = (z == 0) ? g_Qlo : g_Klo;
        #pragma unroll
        for (int i = 0; i < 32; i++) {
            int s = tid + i * NT;          // 0..8191 pair slots
            int m = s >> 6, c2 = (s & 63) * 2;
            float a = stage[m * 132 + c2]     + __ldg(&bias[col0 + c2]);
            float b = stage[m * 132 + c2 + 1] + __ldg(&bias[col0 + c2 + 1]);
            __nv_bfloat162 h, l2;
            split2(a, b, h, l2);
            size_t idx = ((size_t)(row0 + m) * H + col0 + c2) >> 1;
            ((__nv_bfloat162*)ohi)[idx] = h;
            ((__nv_bfloat162*)olo)[idx] = l2;
        }
    } else {
        // V: write transposed [b][h][s]
        #pragma unroll
        for (int i = 0; i < 32; i++) {
            int p = tid + i * NT;          // 0..8191 pair slots
            int c = p >> 6, mp = (p & 63) * 2;
            float bs = __ldg(&bias[col0 + c]);
            float a = stage[mp * 132 + c] + bs;
            float b = stage[(mp + 1) * 132 + c] + bs;
            __nv_bfloat162 h, l2;
            split2(a, b, h, l2);
            size_t idx = (((size_t)(row0 >> 12) * H + col0 + c) * SQ +
                          (row0 & 4095) + mp) >> 1;
            ((__nv_bfloat162*)g_Vthi)[idx] = h;
            ((__nv_bfloat162*)g_Vtlo)[idx] = l2;
        }
    }
}

// ---------------------------------------------------------------------------
// Scores GEMM: g_P = Q K^T * scale, masked. grid (SQ/128, SQ/128, NB)
// ---------------------------------------------------------------------------
__global__ __launch_bounds__(NT) void scores_mm(const int* __restrict__ mask)
{
    extern __shared__ char dsm[];
    uint32_t sbuf = smem_u32(dsm);
    const int tid = threadIdx.x;
    const int bz = blockIdx.z, row0 = blockIdx.y * 128, col0 = blockIdx.x * 128;

    const __nv_bfloat16* Ah = g_Qhi + ((size_t)bz * SQ + row0) * H;
    const __nv_bfloat16* Al = g_Qlo + ((size_t)bz * SQ + row0) * H;
    const __nv_bfloat16* Bh = g_Khi + ((size_t)bz * SQ + col0) * H;
    const __nv_bfloat16* Bl = g_Klo + ((size_t)bz * SQ + col0) * H;

    float acc[2][8][4] = {};
    gemm_main(Ah, Al, Bh, Bl, H, H, H / 64, sbuf, acc);

    float* stage = (float*)dsm;
    store_stage(stage, acc);
    __syncthreads();

    const float scale = 0.03125f;  // 1/sqrt(1024)
    const size_t pbase = (size_t)bz * SQ * SQ;
    #pragma unroll
    for (int i = 0; i < 64; i++) {
        int s = tid + i * NT;              // 0..16383
        int m = s >> 7, c = s & 127;
        size_t gidx = pbase + (size_t)(row0 + m) * SQ + col0 + c;
        float v = stage[m * 132 + c] * scale;
        g_P[gidx] = (__ldg(&mask[gidx]) == 0) ? -CUDART_INF_F : v;
    }
}

// ---------------------------------------------------------------------------
// Row softmax of g_P -> split bf16 P. One block per row.
// ---------------------------------------------------------------------------
__global__ __launch_bounds__(256) void softmax_k()
{
    __shared__ float buf[SQ];
    __shared__ float red[8];

    const int tid = threadIdx.x;
    const float* p = g_P + (size_t)blockIdx.x * SQ;

    float m = -CUDART_INF_F;
    for (int i = tid; i < SQ; i += 256) {
        float v = p[i];
        buf[i] = v;
        m = fmaxf(m, v);
    }
    #pragma unroll
    for (int o = 16; o; o >>= 1) m = fmaxf(m, __shfl_xor_sync(0xFFFFFFFFu, m, o));
    if ((tid & 31) == 0) red[tid >> 5] = m;
    __syncthreads();
    m = red[0];
    #pragma unroll
    for (int w = 1; w < 8; w++) m = fmaxf(m, red[w]);
    __syncthreads();

    float s = 0.0f;
    for (int i = tid; i < SQ; i += 256) {
        float e = __expf(buf[i] - m);
        buf[i] = e;
        s += e;
    }
    #pragma unroll
    for (int o = 16; o; o >>= 1) s += __shfl_xor_sync(0xFFFFFFFFu, s, o);
    if ((tid & 31) == 0) red[tid >> 5] = s;
    __syncthreads();
    s = red[0];
    #pragma unroll
    for (int w = 1; w < 8; w++) s += red[w];
    float inv = 1.0f / s;

    size_t r2 = (size_t)blockIdx.x * (SQ / 2);
    for (int i = tid; i < SQ / 2; i += 256) {
        float a = buf[2 * i] * inv, b = buf[2 * i + 1] * inv;
        __nv_bfloat162 h, l2;
        split2(a, b, h, l2);
        ((__nv_bfloat162*)g_Phi)[r2 + i] = h;
        ((__nv_bfloat162*)g_Plo)[r2 + i] = l2;
    }
}

// ---------------------------------------------------------------------------
// PV GEMM: out = P @ V (V pre-transposed). grid (H/128, SQ/128, NB)
// ---------------------------------------------------------------------------
__global__ __launch_bounds__(NT) void pv_mm(float* __restrict__ out)
{
    extern __shared__ char dsm[];
    uint32_t sbuf = smem_u32(dsm);
    const int tid = threadIdx.x;
    const int bz = blockIdx.z, row0 = blockIdx.y * 128, col0 = blockIdx.x * 128;

    const __nv_bfloat16* Ah = g_Phi  + (size_t)bz * SQ * SQ + (size_t)row0 * SQ;
    const __nv_bfloat16* Al = g_Plo  + (size_t)bz * SQ * SQ + (size_t)row0 * SQ;
    const __nv_bfloat16* Bh = g_Vthi + ((size_t)bz * H + col0) * SQ;
    const __nv_bfloat16* Bl = g_Vtlo + ((size_t)bz * H + col0) * SQ;

    float acc[2][8][4] = {};
    gemm_main(Ah, Al, Bh, Bl, SQ, SQ, SQ / 64, sbuf, acc);

    float* stage = (float*)dsm;
    store_stage(stage, acc);
    __syncthreads();

    #pragma unroll
    for (int i = 0; i < 64; i++) {
        int s = tid + i * NT;
        int m = s >> 7, c = s & 127;
        out[((size_t)bz * SQ + row0 + m) * H + col0 + c] = stage[m * 132 + c];
    }
}

// ---------------------------------------------------------------------------
extern "C" void kernel_launch(void* const* d_in, const int* in_sizes, int n_in,
                              void* d_out, int out_size)
{
    const float* X    = (const float*)d_in[0];
    const int*   mask = (const int*)  d_in[1];
    const float* Wq   = (const float*)d_in[2];
    const float* bq   = (const float*)d_in[3];
    const float* Wk   = (const float*)d_in[4];
    const float* bk   = (const float*)d_in[5];
    const float* Wv   = (const float*)d_in[6];
    const float* bv   = (const float*)d_in[7];
    float* out = (float*)d_out;

    cudaFuncSetAttribute(qkv_mm,    cudaFuncAttributeMaxDynamicSharedMemorySize, SMEM_DYN);
    cudaFuncSetAttribute(scores_mm, cudaFuncAttributeMaxDynamicSharedMemorySize, SMEM_DYN);
    cudaFuncSetAttribute(pv_mm,     cudaFuncAttributeMaxDynamicSharedMemorySize, SMEM_DYN);

    // Resolve device-global scratch addresses (host-side, capture-safe)
    __nv_bfloat16 *pXhi, *pXlo, *pWhi, *pWlo;
    cudaGetSymbolAddress((void**)&pXhi, g_Xhi);
    cudaGetSymbolAddress((void**)&pXlo, g_Xlo);
    cudaGetSymbolAddress((void**)&pWhi, g_Whi);
    cudaGetSymbolAddress((void**)&pWlo, g_Wlo);

    // Split inputs into bf16 hi/lo
    split_k<<<(MTOT * E / 4) / NT, NT>>>(X, pXhi, pXlo, MTOT * E / 4);
    split_k<<<(H * E / 4) / NT, NT>>>(Wq, pWhi,                 pWlo,                 H * E / 4);
    split_k<<<(H * E / 4) / NT, NT>>>(Wk, pWhi + (size_t)H * E, pWlo + (size_t)H * E, H * E / 4);
    split_k<<<(H * E / 4) / NT, NT>>>(Wv, pWhi + (size_t)2 * H * E, pWlo + (size_t)2 * H * E, H * E / 4);

    qkv_mm<<<dim3(H / 128, MTOT / 128, 3), NT, SMEM_DYN>>>(bq, bk, bv);
    scores_mm<<<dim3(SQ / 128, SQ / 128, NB), NT, SMEM_DYN>>>(mask);
    softmax_k<<<NB * SQ, 256>>>();
    pv_mm<<<dim3(H / 128, SQ / 128, NB), NT, SMEM_DYN>>>(out);
}

// round 4
// speedup vs baseline: 3.1921x; 1.0240x over previous
#include <cuda_runtime.h>
#include <cuda_bf16.h>
#include <cstdint>
#include <math_constants.h>

#define E    1024
#define H    1024
#define SQ   4096
#define NB   2
#define MTOT 8192
#define NT   256
#define SMEM_DYN 131072

// ---------------------------------------------------------------------------
// Device scratch (allocation-free per harness rules)
// ---------------------------------------------------------------------------
__device__ __align__(256) __nv_bfloat16 g_Xhi[(size_t)MTOT * E];
__device__ __align__(256) __nv_bfloat16 g_Xlo[(size_t)MTOT * E];
__device__ __align__(256) __nv_bfloat16 g_Whi[(size_t)3 * H * E];
__device__ __align__(256) __nv_bfloat16 g_Wlo[(size_t)3 * H * E];
__device__ __align__(256) __nv_bfloat16 g_Qhi[(size_t)MTOT * H];
__device__ __align__(256) __nv_bfloat16 g_Qlo[(size_t)MTOT * H];
__device__ __align__(256) __nv_bfloat16 g_Khi[(size_t)MTOT * H];
__device__ __align__(256) __nv_bfloat16 g_Klo[(size_t)MTOT * H];
__device__ __align__(256) __nv_bfloat16 g_Vthi[(size_t)NB * H * SQ]; // [b][h][s]
__device__ __align__(256) __nv_bfloat16 g_Vtlo[(size_t)NB * H * SQ];
__device__ __align__(256) float         g_P  [(size_t)NB * SQ * SQ];
__device__ __align__(256) __nv_bfloat16 g_Phi[(size_t)NB * SQ * SQ];
__device__ __align__(256) __nv_bfloat16 g_Plo[(size_t)NB * SQ * SQ];

// ---------------------------------------------------------------------------
// Helpers
// ---------------------------------------------------------------------------
__device__ __forceinline__ uint32_t smem_u32(const void* p) {
    uint32_t a;
    asm("{ .reg .u64 t; cvta.to.shared.u64 t, %1; cvt.u32.u64 %0, t; }"
        : "=r"(a) : "l"(p));
    return a;
}

#define SWZ(o) ((o) ^ (((o) >> 3) & 0x70))

__device__ __forceinline__ void cpa16(uint32_t dst, const void* src) {
    asm volatile("cp.async.cg.shared.global [%0], [%1], 16;" :: "r"(dst), "l"(src));
}
#define CP_COMMIT() asm volatile("cp.async.commit_group;" ::: "memory")
#define CP_WAIT1()  asm volatile("cp.async.wait_group 1;" ::: "memory")
#define CP_WAIT0()  asm volatile("cp.async.wait_group 0;" ::: "memory")

__device__ __forceinline__ void ldsm4(uint32_t r[4], uint32_t addr) {
    asm volatile("ldmatrix.sync.aligned.m8n8.x4.shared.b16 {%0,%1,%2,%3}, [%4];"
                 : "=r"(r[0]), "=r"(r[1]), "=r"(r[2]), "=r"(r[3]) : "r"(addr));
}

__device__ __forceinline__ void mma16816(float* d, const uint32_t* a,
                                         uint32_t b0, uint32_t b1) {
    asm volatile(
        "mma.sync.aligned.m16n8k16.row.col.f32.bf16.bf16.f32 "
        "{%0,%1,%2,%3}, {%4,%5,%6,%7}, {%8,%9}, {%0,%1,%2,%3};"
        : "+f"(d[0]), "+f"(d[1]), "+f"(d[2]), "+f"(d[3])
        : "r"(a[0]), "r"(a[1]), "r"(a[2]), "r"(a[3]), "r"(b0), "r"(b1));
}

__device__ __forceinline__ void split2(float a, float b,
                                       __nv_bfloat162& h, __nv_bfloat162& l2) {
    h = __float22bfloat162_rn(make_float2(a, b));
    float2 hf = __bfloat1622float2(h);
    l2 = __float22bfloat162_rn(make_float2(a - hf.x, b - hf.y));
}

// Copy one 128x64 bf16 tile (K-major rows) into SW128-swizzled smem
__device__ __forceinline__ void fill_copy(uint32_t dst,
                                          const __nv_bfloat16* __restrict__ src,
                                          size_t ld, int tid) {
    #pragma unroll
    for (int i = 0; i < 4; i++) {
        int s = tid + i * NT;
        int r = s >> 3, q = s & 7;
        cpa16(dst + SWZ((uint32_t)(r * 128 + q * 16)),
              src + (size_t)r * ld + q * 8);
    }
}

// ---------------------------------------------------------------------------
// Shared NT GEMM mainloop: C[128x128] += (Ahi+Alo)(Bhi+Blo)^T, bf16x3.
// Both operands stored K-major (row = M or N index, cols = K).
// MMAs grouped in 3 passes of 16 independent ops (dependency distance 16).
// ---------------------------------------------------------------------------
__device__ __forceinline__ void gemm_main(
    const __nv_bfloat16* __restrict__ Ah, const __nv_bfloat16* __restrict__ Al,
    const __nv_bfloat16* __restrict__ Bh, const __nv_bfloat16* __restrict__ Bl,
    size_t lda, size_t ldb, int nkb, uint32_t sbuf, float (&acc)[2][8][4])
{
    const int tid = threadIdx.x, l = tid & 31, wid = tid >> 5;
    const int mw = (wid >> 1) * 32, nw = (wid & 1) * 64;
    // ldmatrix lane address offsets (bytes, pre-swizzle)
    const uint32_t aoff = (uint32_t)((mw + (l & 15)) * 128 + ((l >> 4) & 1) * 16);
    const uint32_t boff = (uint32_t)((nw + (l & 7) + ((l >> 4) & 1) * 8) * 128 +
                                     ((l >> 3) & 1) * 16);

    // Prologue: stage 0
    fill_copy(sbuf,         Ah, lda, tid);
    fill_copy(sbuf + 16384, Al, lda, tid);
    fill_copy(sbuf + 32768, Bh, ldb, tid);
    fill_copy(sbuf + 49152, Bl, ldb, tid);
    CP_COMMIT();

    for (int kb = 0; kb < nkb; kb++) {
        if (kb + 1 < nkb) {
            uint32_t nbuf = sbuf + ((kb + 1) & 1) * 65536;
            size_t ko = (size_t)(kb + 1) * 64;
            fill_copy(nbuf,         Ah + ko, lda, tid);
            fill_copy(nbuf + 16384, Al + ko, lda, tid);
            fill_copy(nbuf + 32768, Bh + ko, ldb, tid);
            fill_copy(nbuf + 49152, Bl + ko, ldb, tid);
            CP_COMMIT();
            CP_WAIT1();
        } else {
            CP_WAIT0();
        }
        __syncthreads();

        uint32_t base = sbuf + (kb & 1) * 65536;
        #pragma unroll
        for (int c = 0; c < 4; c++) {
            uint32_t ao = 32u * c;
            uint32_t ahi[2][4], alo[2][4], bhi[4][4], blo[4][4];
            // All fragment loads up front (12 ldmatrix.x4)
            ldsm4(ahi[0], base +         SWZ(aoff + ao));
            ldsm4(ahi[1], base +         SWZ(aoff + 2048 + ao));
            ldsm4(alo[0], base + 16384 + SWZ(aoff + ao));
            ldsm4(alo[1], base + 16384 + SWZ(aoff + 2048 + ao));
            #pragma unroll
            for (int j = 0; j < 4; j++) {
                ldsm4(bhi[j], base + 32768 + SWZ(boff + j * 2048 + ao));
                ldsm4(blo[j], base + 49152 + SWZ(boff + j * 2048 + ao));
            }
            // Pass 1: hi*hi (16 independent MMAs)
            #pragma unroll
            for (int j = 0; j < 4; j++)
                #pragma unroll
                for (int mf = 0; mf < 2; mf++) {
                    mma16816(acc[mf][2*j],     ahi[mf], bhi[j][0], bhi[j][1]);
                    mma16816(acc[mf][2*j + 1], ahi[mf], bhi[j][2], bhi[j][3]);
                }
            // Pass 2: hi*lo
            #pragma unroll
            for (int j = 0; j < 4; j++)
                #pragma unroll
                for (int mf = 0; mf < 2; mf++) {
                    mma16816(acc[mf][2*j],     ahi[mf], blo[j][0], blo[j][1]);
                    mma16816(acc[mf][2*j + 1], ahi[mf], blo[j][2], blo[j][3]);
                }
            // Pass 3: lo*hi
            #pragma unroll
            for (int j = 0; j < 4; j++)
                #pragma unroll
                for (int mf = 0; mf < 2; mf++) {
                    mma16816(acc[mf][2*j],     alo[mf], bhi[j][0], bhi[j][1]);
                    mma16816(acc[mf][2*j + 1], alo[mf], bhi[j][2], bhi[j][3]);
                }
        }
        __syncthreads();
    }
}

// Store register accumulators into padded fp32 stage (128 x 132)
__device__ __forceinline__ void store_stage(float* stage, float (&acc)[2][8][4]) {
    const int tid = threadIdx.x, l = tid & 31, wid = tid >> 5;
    const int mw = (wid >> 1) * 32, nw = (wid & 1) * 64;
    const int r0 = mw + (l >> 2), c0 = nw + (l & 3) * 2;
    #pragma unroll
    for (int mf = 0; mf < 2; mf++)
        #pragma unroll
        for (int nf = 0; nf < 8; nf++) {
            int cc = c0 + nf * 8;
            *(float2*)&stage[(r0 + mf * 16) * 132 + cc] =
                make_float2(acc[mf][nf][0], acc[mf][nf][1]);
            *(float2*)&stage[(r0 + mf * 16 + 8) * 132 + cc] =
                make_float2(acc[mf][nf][2], acc[mf][nf][3]);
        }
}

// ---------------------------------------------------------------------------
// Split fp32 -> (hi, lo) bf16. One merged launch: region 0 = X (2M float4),
// regions 1..3 = Wq/Wk/Wv (256K float4 each).
// ---------------------------------------------------------------------------
__global__ __launch_bounds__(NT) void split_k(const float* __restrict__ X,
                                              const float* __restrict__ Wq,
                                              const float* __restrict__ Wk,
                                              const float* __restrict__ Wv,
                                              __nv_bfloat16* __restrict__ Xhi,
                                              __nv_bfloat16* __restrict__ Xlo,
                                              __nv_bfloat16* __restrict__ Whi,
                                              __nv_bfloat16* __restrict__ Wlo)
{
    const int nx = MTOT * E / 4;       // 2M
    const int nw = H * E / 4;          // 256K
    int i = blockIdx.x * NT + threadIdx.x;
    const float* src;
    __nv_bfloat16 *hi, *lo;
    int j;
    if (i < nx) {
        src = X; hi = Xhi; lo = Xlo; j = i;
    } else {
        int t = i - nx;
        int w = t / nw;                // 0..2
        j = t - w * nw;
        src = (w == 0) ? Wq : (w == 1) ? Wk : Wv;
        hi = Whi + (size_t)w * H * E;
        lo = Wlo + (size_t)w * H * E;
    }
    float4 v = ((const float4*)src)[j];
    __nv_bfloat162 h0, l0, h1, l1;
    split2(v.x, v.y, h0, l0);
    split2(v.z, v.w, h1, l1);
    ((__nv_bfloat162*)hi)[2 * j]     = h0;
    ((__nv_bfloat162*)hi)[2 * j + 1] = h1;
    ((__nv_bfloat162*)lo)[2 * j]     = l0;
    ((__nv_bfloat162*)lo)[2 * j + 1] = l1;
}

// ---------------------------------------------------------------------------
// QKV projection GEMM. grid (H/128, MTOT/128, 3)
// ---------------------------------------------------------------------------
__global__ __launch_bounds__(NT) void qkv_mm(const float* __restrict__ bq,
                                             const float* __restrict__ bk,
                                             const float* __restrict__ bv)
{
    extern __shared__ char dsm[];
    uint32_t sbuf = smem_u32(dsm);
    const int tid = threadIdx.x;
    const int z = blockIdx.z, row0 = blockIdx.y * 128, col0 = blockIdx.x * 128;

    const __nv_bfloat16* Ah = g_Xhi + (size_t)row0 * E;
    const __nv_bfloat16* Al = g_Xlo + (size_t)row0 * E;
    const __nv_bfloat16* Bh = g_Whi + ((size_t)z * H + col0) * E;
    const __nv_bfloat16* Bl = g_Wlo + ((size_t)z * H + col0) * E;

    float acc[2][8][4] = {};
    gemm_main(Ah, Al, Bh, Bl, E, E, E / 64, sbuf, acc);

    float* stage = (float*)dsm;
    store_stage(stage, acc);
    __syncthreads();

    const float* bias = (z == 0) ? bq : (z == 1) ? bk : bv;

    if (z < 2) {
        __nv_bfloat16* ohi = (z == 0) ? g_Qhi : g_Khi;
        __nv_bfloat16* olo = (z == 0) ? g_Qlo : g_Klo;
        #pragma unroll
        for (int i = 0; i < 32; i++) {
            int s = tid + i * NT;          // 0..8191 pair slots
            int m = s >> 6, c2 = (s & 63) * 2;
            float a = stage[m * 132 + c2]     + __ldg(&bias[col0 + c2]);
            float b = stage[m * 132 + c2 + 1] + __ldg(&bias[col0 + c2 + 1]);
            __nv_bfloat162 h, l2;
            split2(a, b, h, l2);
            size_t idx = ((size_t)(row0 + m) * H + col0 + c2) >> 1;
            ((__nv_bfloat162*)ohi)[idx] = h;
            ((__nv_bfloat162*)olo)[idx] = l2;
        }
    } else {
        // V: write transposed [b][h][s]
        #pragma unroll
        for (int i = 0; i < 32; i++) {
            int p = tid + i * NT;          // 0..8191 pair slots
            int c = p >> 6, mp = (p & 63) * 2;
            float bs = __ldg(&bias[col0 + c]);
            float a = stage[mp * 132 + c] + bs;
            float b = stage[(mp + 1) * 132 + c] + bs;
            __nv_bfloat162 h, l2;
            split2(a, b, h, l2);
            size_t idx = (((size_t)(row0 >> 12) * H + col0 + c) * SQ +
                          (row0 & 4095) + mp) >> 1;
            ((__nv_bfloat162*)g_Vthi)[idx] = h;
            ((__nv_bfloat162*)g_Vtlo)[idx] = l2;
        }
    }
}

// ---------------------------------------------------------------------------
// Scores GEMM: g_P = Q K^T * scale, masked. grid (SQ/128, SQ/128, NB)
// ---------------------------------------------------------------------------
__global__ __launch_bounds__(NT) void scores_mm(const int* __restrict__ mask)
{
    extern __shared__ char dsm[];
    uint32_t sbuf = smem_u32(dsm);
    const int tid = threadIdx.x;
    const int bz = blockIdx.z, row0 = blockIdx.y * 128, col0 = blockIdx.x * 128;

    const __nv_bfloat16* Ah = g_Qhi + ((size_t)bz * SQ + row0) * H;
    const __nv_bfloat16* Al = g_Qlo + ((size_t)bz * SQ + row0) * H;
    const __nv_bfloat16* Bh = g_Khi + ((size_t)bz * SQ + col0) * H;
    const __nv_bfloat16* Bl = g_Klo + ((size_t)bz * SQ + col0) * H;

    float acc[2][8][4] = {};
    gemm_main(Ah, Al, Bh, Bl, H, H, H / 64, sbuf, acc);

    float* stage = (float*)dsm;
    store_stage(stage, acc);
    __syncthreads();

    const float scale = 0.03125f;  // 1/sqrt(1024)
    const size_t pbase = (size_t)bz * SQ * SQ;
    #pragma unroll
    for (int i = 0; i < 16; i++) {
        int s = tid + i * NT;              // 0..4095 quad slots
        int m = s >> 5, c4 = (s & 31) * 4;
        size_t gidx = pbase + (size_t)(row0 + m) * SQ + col0 + c4;
        int4 mk = __ldg((const int4*)(mask + gidx));
        float4 v;
        v.x = (mk.x == 0) ? -CUDART_INF_F : stage[m * 132 + c4]     * scale;
        v.y = (mk.y == 0) ? -CUDART_INF_F : stage[m * 132 + c4 + 1] * scale;
        v.z = (mk.z == 0) ? -CUDART_INF_F : stage[m * 132 + c4 + 2] * scale;
        v.w = (mk.w == 0) ? -CUDART_INF_F : stage[m * 132 + c4 + 3] * scale;
        *(float4*)(g_P + gidx) = v;
    }
}

// ---------------------------------------------------------------------------
// Row softmax of g_P -> split bf16 P. One block per row.
// ---------------------------------------------------------------------------
__global__ __launch_bounds__(256) void softmax_k()
{
    __shared__ float buf[SQ];
    __shared__ float red[8];

    const int tid = threadIdx.x;
    const float* p = g_P + (size_t)blockIdx.x * SQ;

    float m = -CUDART_INF_F;
    for (int i = tid; i < SQ; i += 256) {
        float v = p[i];
        buf[i] = v;
        m = fmaxf(m, v);
    }
    #pragma unroll
    for (int o = 16; o; o >>= 1) m = fmaxf(m, __shfl_xor_sync(0xFFFFFFFFu, m, o));
    if ((tid & 31) == 0) red[tid >> 5] = m;
    __syncthreads();
    m = red[0];
    #pragma unroll
    for (int w = 1; w < 8; w++) m = fmaxf(m, red[w]);
    __syncthreads();

    float s = 0.0f;
    for (int i = tid; i < SQ; i += 256) {
        float e = __expf(buf[i] - m);
        buf[i] = e;
        s += e;
    }
    #pragma unroll
    for (int o = 16; o; o >>= 1) s += __shfl_xor_sync(0xFFFFFFFFu, s, o);
    if ((tid & 31) == 0) red[tid >> 5] = s;
    __syncthreads();
    s = red[0];
    #pragma unroll
    for (int w = 1; w < 8; w++) s += red[w];
    float inv = 1.0f / s;

    size_t r2 = (size_t)blockIdx.x * (SQ / 2);
    for (int i = tid; i < SQ / 2; i += 256) {
        float a = buf[2 * i] * inv, b = buf[2 * i + 1] * inv;
        __nv_bfloat162 h, l2;
        split2(a, b, h, l2);
        ((__nv_bfloat162*)g_Phi)[r2 + i] = h;
        ((__nv_bfloat162*)g_Plo)[r2 + i] = l2;
    }
}

// ---------------------------------------------------------------------------
// PV GEMM: out = P @ V (V pre-transposed). grid (H/128, SQ/128, NB)
// ---------------------------------------------------------------------------
__global__ __launch_bounds__(NT) void pv_mm(float* __restrict__ out)
{
    extern __shared__ char dsm[];
    uint32_t sbuf = smem_u32(dsm);
    const int tid = threadIdx.x;
    const int bz = blockIdx.z, row0 = blockIdx.y * 128, col0 = blockIdx.x * 128;

    const __nv_bfloat16* Ah = g_Phi  + (size_t)bz * SQ * SQ + (size_t)row0 * SQ;
    const __nv_bfloat16* Al = g_Plo  + (size_t)bz * SQ * SQ + (size_t)row0 * SQ;
    const __nv_bfloat16* Bh = g_Vthi + ((size_t)bz * H + col0) * SQ;
    const __nv_bfloat16* Bl = g_Vtlo + ((size_t)bz * H + col0) * SQ;

    float acc[2][8][4] = {};
    gemm_main(Ah, Al, Bh, Bl, SQ, SQ, SQ / 64, sbuf, acc);

    float* stage = (float*)dsm;
    store_stage(stage, acc);
    __syncthreads();

    #pragma unroll
    for (int i = 0; i < 16; i++) {
        int s = tid + i * NT;
        int m = s >> 5, c4 = (s & 31) * 4;
        float4 v = *(float4*)&stage[m * 132 + c4];
        *(float4*)&out[((size_t)bz * SQ + row0 + m) * H + col0 + c4] = v;
    }
}

// ---------------------------------------------------------------------------
extern "C" void kernel_launch(void* const* d_in, const int* in_sizes, int n_in,
                              void* d_out, int out_size)
{
    const float* X    = (const float*)d_in[0];
    const int*   mask = (const int*)  d_in[1];
    const float* Wq   = (const float*)d_in[2];
    const float* bq   = (const float*)d_in[3];
    const float* Wk   = (const float*)d_in[4];
    const float* bk   = (const float*)d_in[5];
    const float* Wv   = (const float*)d_in[6];
    const float* bv   = (const float*)d_in[7];
    float* out = (float*)d_out;

    cudaFuncSetAttribute(qkv_mm,    cudaFuncAttributeMaxDynamicSharedMemorySize, SMEM_DYN);
    cudaFuncSetAttribute(scores_mm, cudaFuncAttributeMaxDynamicSharedMemorySize, SMEM_DYN);
    cudaFuncSetAttribute(pv_mm,     cudaFuncAttributeMaxDynamicSharedMemorySize, SMEM_DYN);

    // Resolve device-global scratch addresses (host-side, capture-safe)
    __nv_bfloat16 *pXhi, *pXlo, *pWhi, *pWlo;
    cudaGetSymbolAddress((void**)&pXhi, g_Xhi);
    cudaGetSymbolAddress((void**)&pXlo, g_Xlo);
    cudaGetSymbolAddress((void**)&pWhi, g_Whi);
    cudaGetSymbolAddress((void**)&pWlo, g_Wlo);

    // Split all fp32 inputs into bf16 hi/lo (one merged launch)
    int total4 = (MTOT * E + 3 * H * E) / 4;
    split_k<<<total4 / NT, NT>>>(X, Wq, Wk, Wv, pXhi, pXlo, pWhi, pWlo);

    qkv_mm<<<dim3(H / 128, MTOT / 128, 3), NT, SMEM_DYN>>>(bq, bk, bv);
    scores_mm<<<dim3(SQ / 128, SQ / 128, NB), NT, SMEM_DYN>>>(mask);
    softmax_k<<<NB * SQ, 256>>>();
    pv_mm<<<dim3(H / 128, SQ / 128, NB), NT, SMEM_DYN>>>(out);
}